// round 9
// baseline (speedup 1.0000x reference)
#include <cuda_runtime.h>
#include <cstdio>
#include <cstdint>

#define B_ 2
#define S_ 2048
#define D_ 1024
#define H_ 16
#define HD_ 64
#define NKB_ 32   // S_/64 key blocks

// ---------------- scratch (device globals; no allocation allowed) ----------------
__device__ float g_q[(size_t)B_ * H_ * S_ * HD_];     // [B,H,S,Hd]
__device__ float g_kT[(size_t)B_ * H_ * HD_ * S_];    // [B,H,Hd,S]
__device__ float g_v[(size_t)B_ * H_ * S_ * HD_];     // [B,H,S,Hd]
__device__ float g_attn[(size_t)B_ * S_ * D_];        // [B,S,D]
__device__ float g_scores[(size_t)B_ * H_ * S_ * S_]; // fallback weights buffer
__device__ float g_mkb[(size_t)B_ * H_ * S_ * NKB_];  // running max at each kb
__device__ float g_mfin[(size_t)B_ * H_ * S_];        // final max per row
__device__ float g_linv[(size_t)B_ * H_ * S_];        // 1/l per row

// ---------------- helpers ----------------
__device__ __forceinline__ uint32_t f2tf32(float x) {
    uint32_t u;
    asm("cvt.rna.tf32.f32 %0, %1;" : "=r"(u) : "f"(x));
    return u;
}

__device__ __forceinline__ void mma_tf32(float& c0, float& c1, float& c2, float& c3,
                                         uint32_t a0, uint32_t a1, uint32_t a2, uint32_t a3,
                                         uint32_t b0, uint32_t b1) {
    asm volatile(
        "mma.sync.aligned.m16n8k8.row.col.f32.tf32.tf32.f32 "
        "{%0,%1,%2,%3}, {%4,%5,%6,%7}, {%8,%9}, {%0,%1,%2,%3};"
        : "+f"(c0), "+f"(c1), "+f"(c2), "+f"(c3)
        : "r"(a0), "r"(a1), "r"(a2), "r"(a3), "r"(b0), "r"(b1));
}

#define ASTRIDE 132   // A-frag: 32 lanes x 4 slots = 128 + 4 pad
#define BSTRIDE 66    // B-frag: 32 lanes x 2 slots = 64 + 2 pad

// ---------------- epilogue for QKV projection ----------------
struct EpiQKV {
    const float* bias;
    __device__ __forceinline__ void operator()(int m, int n, float v) const {
        v += bias[n];
        int part = n >> 10;
        int rem = n & 1023;
        int h = rem >> 6;
        int d = rem & 63;
        int b = m >> 11;
        int s = m & 2047;
        size_t bh = (size_t)(b * H_ + h);
        if (part == 0)
            g_q[(bh * S_ + s) * HD_ + d] = v;
        else if (part == 1)
            g_kT[(bh * HD_ + d) * S_ + s] = v;
        else
            g_v[(bh * S_ + s) * HD_ + d] = v;
    }
};

struct EpiOut {
    const float* bias;
    float* out;
    __device__ __forceinline__ void operator()(int m, int n, float v) const {
        out[(size_t)m * D_ + n] = v + bias[n];
    }
};

// ---------------- tf32 GEMM, 4 warps x (64x64) warp tiles, BM=BN=128 BK=32 ------
// Frag redundancy A x2 + B x2 (was x4/x2): 96KB smem traffic per tile vs 128KB.
template <class Epi>
__global__ void __launch_bounds__(128, 2)
tgemm_kernel(const float* __restrict__ A, const float* __restrict__ Bp,
             int K, int lda, int ldb, Epi epi) {
    __shared__ uint32_t sA[32 * ASTRIDE];   // 8 m-tiles x 4 ksteps
    __shared__ uint32_t sB[64 * BSTRIDE];   // 16 n-tiles x 4 ksteps

    const int tid = threadIdx.x;
    const int lane = tid & 31;
    const int warp = tid >> 5;
    const int wm = warp >> 1;   // 0..1
    const int wn = warp & 1;    // 0..1
    const int row0 = blockIdx.y * 128;
    const int col0 = blockIdx.x * 128;

    float acc[4][8][4];
#pragma unroll
    for (int i = 0; i < 4; i++)
#pragma unroll
        for (int j = 0; j < 8; j++)
#pragma unroll
            for (int v = 0; v < 4; v++) acc[i][j][v] = 0.f;

    for (int k0 = 0; k0 < K; k0 += 32) {
        // ---- stage A (fp32 -> tf32 fragment-major) ----
#pragma unroll
        for (int it = 0; it < 8; ++it) {
            int idx = tid + it * 128;
            int r = idx >> 3, c4 = (idx & 7) << 2;
            float4 val = *reinterpret_cast<const float4*>(
                &A[(size_t)(row0 + r) * lda + k0 + c4]);
            int mt = r >> 4, rw = r & 15;
            float vv[4] = {val.x, val.y, val.z, val.w};
#pragma unroll
            for (int j = 0; j < 4; j++) {
                int c = c4 + j;
                int ks = c >> 3, ci = c & 7;
                int ln = ((rw & 7) << 2) | (ci & 3);
                int slot = (rw >> 3) | ((ci >> 2) << 1);
                sA[((mt << 2) + ks) * ASTRIDE + ln * 4 + slot] = f2tf32(vv[j]);
            }
        }
        // ---- stage B ----
#pragma unroll
        for (int it = 0; it < 8; ++it) {
            int idx = tid + it * 128;
            int r = idx >> 5, c4 = (idx & 31) << 2;
            float4 val = *reinterpret_cast<const float4*>(
                &Bp[(size_t)(k0 + r) * ldb + col0 + c4]);
            int ks = r >> 3, rw = r & 7;
            float vv[4] = {val.x, val.y, val.z, val.w};
#pragma unroll
            for (int j = 0; j < 4; j++) {
                int n = c4 + j;
                int nt = n >> 3, ci = n & 7;
                int ln = (ci << 2) | (rw & 3);
                int slot = rw >> 2;
                sB[((nt << 2) + ks) * BSTRIDE + ln * 2 + slot] = f2tf32(vv[j]);
            }
        }
        __syncthreads();

        // ---- compute ----
#pragma unroll
        for (int ks = 0; ks < 4; ks++) {
            uint4 af[4];
            uint2 bf[8];
#pragma unroll
            for (int i = 0; i < 4; i++)
                af[i] = *reinterpret_cast<const uint4*>(
                    &sA[((wm * 4 + i) * 4 + ks) * ASTRIDE + lane * 4]);
#pragma unroll
            for (int j = 0; j < 8; j++)
                bf[j] = *reinterpret_cast<const uint2*>(
                    &sB[((wn * 8 + j) * 4 + ks) * BSTRIDE + lane * 2]);
#pragma unroll
            for (int i = 0; i < 4; i++)
#pragma unroll
                for (int j = 0; j < 8; j++)
                    mma_tf32(acc[i][j][0], acc[i][j][1], acc[i][j][2], acc[i][j][3],
                             af[i].x, af[i].y, af[i].z, af[i].w, bf[j].x, bf[j].y);
        }
        __syncthreads();
    }

#pragma unroll
    for (int i = 0; i < 4; i++) {
        int m0 = row0 + wm * 64 + i * 16 + (lane >> 2);
#pragma unroll
        for (int j = 0; j < 8; j++) {
            int n0 = col0 + wn * 64 + j * 8 + ((lane & 3) << 1);
            epi(m0, n0, acc[i][j][0]);
            epi(m0, n0 + 1, acc[i][j][1]);
            epi(m0 + 8, n0, acc[i][j][2]);
            epi(m0 + 8, n0 + 1, acc[i][j][3]);
        }
    }
}

// ---------------- fused tail: out-proj tiles + weight rescale, one kernel --------
// blocks [0,256): out-projection 128x128 tiles (C = g_attn @ W_out + b).
// blocks [256, 256+65536): rescale one weights row each: w *= exp(m_kb-m_fin)/l.
#define TAIL_GEMM_BLOCKS 256
__global__ void __launch_bounds__(128, 2)
fused_tail_kernel(const float* __restrict__ Ain, const float* __restrict__ W,
                  const float* __restrict__ bias, float* __restrict__ out,
                  float* __restrict__ w) {
    __shared__ uint32_t sA[32 * ASTRIDE];
    __shared__ uint32_t sB[64 * BSTRIDE];
    __shared__ float sfac[NKB_];

    const int bid = blockIdx.x;
    const int tid = threadIdx.x;

    if (bid >= TAIL_GEMM_BLOCKS) {
        // ---------- rescale path ----------
        const size_t row = bid - TAIL_GEMM_BLOCKS;
        if (tid < NKB_)
            sfac[tid] = __expf(g_mkb[row * NKB_ + tid] - g_mfin[row]) * g_linv[row];
        __syncthreads();
        float* d = w + row * S_;
#pragma unroll
        for (int seg = 0; seg < 4; seg++) {
            int c = tid * 4 + seg * 512;
            float4 a = *reinterpret_cast<const float4*>(d + c);
            float f = sfac[c >> 6];
            a.x *= f; a.y *= f; a.z *= f; a.w *= f;
            *reinterpret_cast<float4*>(d + c) = a;
        }
        return;
    }

    // ---------- out-projection GEMM path ----------
    const int lane = tid & 31;
    const int warp = tid >> 5;
    const int wm = warp >> 1;
    const int wn = warp & 1;
    const int row0 = (bid >> 3) * 128;
    const int col0 = (bid & 7) * 128;

    float acc[4][8][4];
#pragma unroll
    for (int i = 0; i < 4; i++)
#pragma unroll
        for (int j = 0; j < 8; j++)
#pragma unroll
            for (int v = 0; v < 4; v++) acc[i][j][v] = 0.f;

    for (int k0 = 0; k0 < D_; k0 += 32) {
#pragma unroll
        for (int it = 0; it < 8; ++it) {
            int idx = tid + it * 128;
            int r = idx >> 3, c4 = (idx & 7) << 2;
            float4 val = *reinterpret_cast<const float4*>(
                &Ain[(size_t)(row0 + r) * D_ + k0 + c4]);
            int mt = r >> 4, rw = r & 15;
            float vv[4] = {val.x, val.y, val.z, val.w};
#pragma unroll
            for (int j = 0; j < 4; j++) {
                int c = c4 + j;
                int ks = c >> 3, ci = c & 7;
                int ln = ((rw & 7) << 2) | (ci & 3);
                int slot = (rw >> 3) | ((ci >> 2) << 1);
                sA[((mt << 2) + ks) * ASTRIDE + ln * 4 + slot] = f2tf32(vv[j]);
            }
        }
#pragma unroll
        for (int it = 0; it < 8; ++it) {
            int idx = tid + it * 128;
            int r = idx >> 5, c4 = (idx & 31) << 2;
            float4 val = *reinterpret_cast<const float4*>(
                &W[(size_t)(k0 + r) * D_ + col0 + c4]);
            int ks = r >> 3, rw = r & 7;
            float vv[4] = {val.x, val.y, val.z, val.w};
#pragma unroll
            for (int j = 0; j < 4; j++) {
                int n = c4 + j;
                int nt = n >> 3, ci = n & 7;
                int ln = (ci << 2) | (rw & 3);
                int slot = rw >> 2;
                sB[((nt << 2) + ks) * BSTRIDE + ln * 2 + slot] = f2tf32(vv[j]);
            }
        }
        __syncthreads();

#pragma unroll
        for (int ks = 0; ks < 4; ks++) {
            uint4 af[4];
            uint2 bf[8];
#pragma unroll
            for (int i = 0; i < 4; i++)
                af[i] = *reinterpret_cast<const uint4*>(
                    &sA[((wm * 4 + i) * 4 + ks) * ASTRIDE + lane * 4]);
#pragma unroll
            for (int j = 0; j < 8; j++)
                bf[j] = *reinterpret_cast<const uint2*>(
                    &sB[((wn * 8 + j) * 4 + ks) * BSTRIDE + lane * 2]);
#pragma unroll
            for (int i = 0; i < 4; i++)
#pragma unroll
                for (int j = 0; j < 8; j++)
                    mma_tf32(acc[i][j][0], acc[i][j][1], acc[i][j][2], acc[i][j][3],
                             af[i].x, af[i].y, af[i].z, af[i].w, bf[j].x, bf[j].y);
        }
        __syncthreads();
    }

#pragma unroll
    for (int i = 0; i < 4; i++) {
        int m0 = row0 + wm * 64 + i * 16 + (lane >> 2);
#pragma unroll
        for (int j = 0; j < 8; j++) {
            int n0 = col0 + wn * 64 + j * 8 + ((lane & 3) << 1);
            out[(size_t)m0 * D_ + n0] = acc[i][j][0] + bias[n0];
            out[(size_t)m0 * D_ + n0 + 1] = acc[i][j][1] + bias[n0 + 1];
            out[(size_t)(m0 + 8) * D_ + n0] = acc[i][j][2] + bias[n0];
            out[(size_t)(m0 + 8) * D_ + n0 + 1] = acc[i][j][3] + bias[n0 + 1];
        }
    }
}

// ---------------- single-pass flash attention (R7, passing) --------------------
#define SMEM_ATTN_BYTES 104960
__global__ void __launch_bounds__(256, 2)
fused_attn_kernel(const float* __restrict__ qg, const float* __restrict__ kTg,
                  const float* __restrict__ vg, float* __restrict__ wout,
                  float* __restrict__ og) {
    extern __shared__ uint32_t smem[];
    uint32_t* sQ = smem;
    uint32_t* sW = smem + 8448;
    uint32_t* sK = smem + 16896;
    uint32_t* sV = smem + 21120;
    float* sm = (float*)(smem + 25344);
    float* sl = (float*)(smem + 25472);
    float* sredm = (float*)(smem + 25728);
    float* sredl = (float*)(smem + 25984);

    const int tid = threadIdx.x;
    const int lane = tid & 31;
    const int warp = tid >> 5;
    const int wm = warp >> 1;
    const int wn = warp & 1;
    const int g = lane >> 2;
    const int qd = lane & 3;
    const int row0 = blockIdx.x * 128;
    const int bh = blockIdx.y;

    const float* Q = qg + (size_t)bh * S_ * HD_;
    const float* KT = kTg + (size_t)bh * HD_ * S_;
    const float* V = vg + (size_t)bh * S_ * HD_;

    auto stageK = [&](int col0k) {
#pragma unroll
        for (int it = 0; it < 4; it++) {
            int idx = tid + it * 256;
            int r = idx >> 4, c4 = (idx & 15) << 2;
            float4 val = *reinterpret_cast<const float4*>(&KT[(size_t)r * S_ + col0k + c4]);
            int ks = r >> 3, rw = r & 7;
            float vv[4] = {val.x, val.y, val.z, val.w};
#pragma unroll
            for (int j = 0; j < 4; j++) {
                int n = c4 + j, nt = n >> 3, ci = n & 7;
                int ln = (ci << 2) | (rw & 3);
                int slot = rw >> 2;
                sK[((nt << 3) + ks) * BSTRIDE + ln * 2 + slot] = f2tf32(vv[j]);
            }
        }
    };
    auto stageV = [&](int col0k) {
#pragma unroll
        for (int it = 0; it < 4; it++) {
            int idx = tid + it * 256;
            int r = idx >> 4, c4 = (idx & 15) << 2;
            float4 val = *reinterpret_cast<const float4*>(&V[(size_t)(col0k + r) * HD_ + c4]);
            int ks = r >> 3, rw = r & 7;
            float vv[4] = {val.x, val.y, val.z, val.w};
#pragma unroll
            for (int j = 0; j < 4; j++) {
                int n = c4 + j, nt = n >> 3, ci = n & 7;
                int ln = (ci << 2) | (rw & 3);
                int slot = rw >> 2;
                sV[((nt << 3) + ks) * BSTRIDE + ln * 2 + slot] = f2tf32(vv[j]);
            }
        }
    };

#pragma unroll
    for (int it = 0; it < 8; it++) {
        int idx = tid + it * 256;
        int r = idx >> 4, c4 = (idx & 15) << 2;
        float4 val = *reinterpret_cast<const float4*>(&Q[(size_t)(row0 + r) * HD_ + c4]);
        int mt = r >> 4, rw = r & 15;
        float vv[4] = {val.x, val.y, val.z, val.w};
#pragma unroll
        for (int j = 0; j < 4; j++) {
            int c = c4 + j, ks = c >> 3, ci = c & 7;
            int ln = ((rw & 7) << 2) | (ci & 3);
            int slot = (rw >> 3) | ((ci >> 2) << 1);
            sQ[((mt << 3) + ks) * ASTRIDE + ln * 4 + slot] = f2tf32(vv[j] * 0.125f);
        }
    }
    if (tid < 128) { sm[tid] = -1e30f; sl[tid] = 0.f; }
    stageK(0);
    stageV(0);

    float acc_o[2][4][4];
#pragma unroll
    for (int i = 0; i < 2; i++)
#pragma unroll
        for (int j = 0; j < 4; j++)
#pragma unroll
            for (int v = 0; v < 4; v++) acc_o[i][j][v] = 0.f;
    __syncthreads();

    for (int kb = 0; kb < NKB_; kb++) {
        const int col0k = kb * 64;

        float sacc[2][4][4];
#pragma unroll
        for (int i = 0; i < 2; i++)
#pragma unroll
            for (int j = 0; j < 4; j++)
#pragma unroll
                for (int v = 0; v < 4; v++) sacc[i][j][v] = 0.f;
#pragma unroll
        for (int ks = 0; ks < 8; ks++) {
            uint4 af[2];
            uint2 bf[4];
#pragma unroll
            for (int i = 0; i < 2; i++)
                af[i] = *reinterpret_cast<const uint4*>(
                    &sQ[((wm * 2 + i) * 8 + ks) * ASTRIDE + lane * 4]);
#pragma unroll
            for (int j = 0; j < 4; j++)
                bf[j] = *reinterpret_cast<const uint2*>(
                    &sK[((wn * 4 + j) * 8 + ks) * BSTRIDE + lane * 2]);
#pragma unroll
            for (int i = 0; i < 2; i++)
#pragma unroll
                for (int j = 0; j < 4; j++)
                    mma_tf32(sacc[i][j][0], sacc[i][j][1], sacc[i][j][2], sacc[i][j][3],
                             af[i].x, af[i].y, af[i].z, af[i].w, bf[j].x, bf[j].y);
        }

#pragma unroll
        for (int i = 0; i < 2; i++) {
            int r0 = wm * 32 + i * 16 + g;
            float mx0 = -1e30f, mx1 = -1e30f;
#pragma unroll
            for (int j = 0; j < 4; j++) {
                mx0 = fmaxf(mx0, fmaxf(sacc[i][j][0], sacc[i][j][1]));
                mx1 = fmaxf(mx1, fmaxf(sacc[i][j][2], sacc[i][j][3]));
            }
            mx0 = fmaxf(mx0, __shfl_xor_sync(0xffffffffu, mx0, 1));
            mx0 = fmaxf(mx0, __shfl_xor_sync(0xffffffffu, mx0, 2));
            mx1 = fmaxf(mx1, __shfl_xor_sync(0xffffffffu, mx1, 1));
            mx1 = fmaxf(mx1, __shfl_xor_sync(0xffffffffu, mx1, 2));
            if (qd == 0) {
                sredm[wn * 128 + r0] = mx0;
                sredm[wn * 128 + r0 + 8] = mx1;
            }
        }
        __syncthreads();

#pragma unroll
        for (int i = 0; i < 2; i++) {
            int r0 = wm * 32 + i * 16 + g;
            float mo0 = sm[r0], mo1 = sm[r0 + 8];
            float mn0 = fmaxf(mo0, fmaxf(sredm[r0], sredm[128 + r0]));
            float mn1 = fmaxf(mo1, fmaxf(sredm[r0 + 8], sredm[128 + r0 + 8]));
            float a0 = __expf(mo0 - mn0), a1 = __expf(mo1 - mn1);
            float s0 = 0.f, s1 = 0.f;
#pragma unroll
            for (int j = 0; j < 4; j++) {
                int c0 = wn * 32 + j * 8 + qd * 2;
                float p00 = __expf(sacc[i][j][0] - mn0);
                float p01 = __expf(sacc[i][j][1] - mn0);
                float p10 = __expf(sacc[i][j][2] - mn1);
                float p11 = __expf(sacc[i][j][3] - mn1);
                s0 += p00 + p01;
                s1 += p10 + p11;
                size_t base = ((size_t)bh * S_ + row0 + r0) * S_ + col0k + c0;
                float2 q0 = {p00, p01};
                float2 q1 = {p10, p11};
                *reinterpret_cast<float2*>(&wout[base]) = q0;
                *reinterpret_cast<float2*>(&wout[base + (size_t)8 * S_]) = q1;
                {
                    int rr = r0, rw2 = rr & 15, mt = rr >> 4;
                    int c = c0, ks = c >> 3, ci = c & 7;
                    int ln = ((rw2 & 7) << 2) | (ci & 3);
                    int slot = (rw2 >> 3) | ((ci >> 2) << 1);
                    sW[((mt << 3) + ks) * ASTRIDE + ln * 4 + slot] = f2tf32(p00);
                    ci = (c + 1) & 7;
                    ln = ((rw2 & 7) << 2) | (ci & 3);
                    slot = (rw2 >> 3) | ((ci >> 2) << 1);
                    sW[((mt << 3) + ks) * ASTRIDE + ln * 4 + slot] = f2tf32(p01);
                    rr = r0 + 8; rw2 = rr & 15; mt = rr >> 4;
                    ci = c & 7;
                    ln = ((rw2 & 7) << 2) | (ci & 3);
                    slot = (rw2 >> 3) | ((ci >> 2) << 1);
                    sW[((mt << 3) + ks) * ASTRIDE + ln * 4 + slot] = f2tf32(p10);
                    ci = (c + 1) & 7;
                    ln = ((rw2 & 7) << 2) | (ci & 3);
                    slot = (rw2 >> 3) | ((ci >> 2) << 1);
                    sW[((mt << 3) + ks) * ASTRIDE + ln * 4 + slot] = f2tf32(p11);
                }
                acc_o[i][j][0] *= a0; acc_o[i][j][1] *= a0;
                acc_o[i][j][2] *= a1; acc_o[i][j][3] *= a1;
            }
            s0 += __shfl_xor_sync(0xffffffffu, s0, 1);
            s0 += __shfl_xor_sync(0xffffffffu, s0, 2);
            s1 += __shfl_xor_sync(0xffffffffu, s1, 1);
            s1 += __shfl_xor_sync(0xffffffffu, s1, 2);
            if (qd == 0) {
                sredl[wn * 128 + r0] = s0;
                sredl[wn * 128 + r0 + 8] = s1;
            }
        }
        __syncthreads();

        if (tid < 128) {
            float mo = sm[tid];
            float mn = fmaxf(mo, fmaxf(sredm[tid], sredm[128 + tid]));
            sl[tid] = sl[tid] * __expf(mo - mn) + sredl[tid] + sredl[128 + tid];
            sm[tid] = mn;
            g_mkb[((size_t)bh * S_ + row0 + tid) * NKB_ + kb] = mn;
        }

        if (kb + 1 < NKB_) stageK(col0k + 64);

#pragma unroll
        for (int ks = 0; ks < 8; ks++) {
            uint4 af[2];
            uint2 bf[4];
#pragma unroll
            for (int i = 0; i < 2; i++)
                af[i] = *reinterpret_cast<const uint4*>(
                    &sW[((wm * 2 + i) * 8 + ks) * ASTRIDE + lane * 4]);
#pragma unroll
            for (int j = 0; j < 4; j++)
                bf[j] = *reinterpret_cast<const uint2*>(
                    &sV[((wn * 4 + j) * 8 + ks) * BSTRIDE + lane * 2]);
#pragma unroll
            for (int i = 0; i < 2; i++)
#pragma unroll
                for (int j = 0; j < 4; j++)
                    mma_tf32(acc_o[i][j][0], acc_o[i][j][1], acc_o[i][j][2], acc_o[i][j][3],
                             af[i].x, af[i].y, af[i].z, af[i].w, bf[j].x, bf[j].y);
        }
        __syncthreads();

        if (kb + 1 < NKB_) stageV(col0k + 64);
    }

    if (tid < 128) {
        float inv = 1.0f / sl[tid];
        sl[tid] = inv;
        g_linv[(size_t)bh * S_ + row0 + tid] = inv;
        g_mfin[(size_t)bh * S_ + row0 + tid] = sm[tid];
    }
    __syncthreads();

    const int b = bh >> 4;
    const int h = bh & 15;
#pragma unroll
    for (int i = 0; i < 2; i++) {
        int r0 = wm * 32 + i * 16 + g;
        float il0 = sl[r0], il1 = sl[r0 + 8];
        int gr = row0 + r0;
#pragma unroll
        for (int j = 0; j < 4; j++) {
            int c0 = wn * 32 + j * 8 + qd * 2;
            float2 p0 = {acc_o[i][j][0] * il0, acc_o[i][j][1] * il0};
            float2 p1 = {acc_o[i][j][2] * il1, acc_o[i][j][3] * il1};
            size_t a0 = (((size_t)b * S_ + gr) * H_ + h) * HD_ + c0;
            size_t a1 = (((size_t)b * S_ + gr + 8) * H_ + h) * HD_ + c0;
            *reinterpret_cast<float2*>(&og[a0]) = p0;
            *reinterpret_cast<float2*>(&og[a1]) = p1;
        }
    }
}

// ---------------- launch ----------------
extern "C" void kernel_launch(void* const* d_in, const int* in_sizes, int n_in,
                              void* d_out, int out_size) {
    const float* query = (const float*)d_in[0];
    const float* W_qkv = (const float*)d_in[1];
    const float* b_qkv = (const float*)d_in[2];
    const float* W_out = (const float*)d_in[3];
    const float* b_out = (const float*)d_in[4];
    float* out = (float*)d_out;

    const size_t OUT_ELEMS = (size_t)B_ * S_ * D_;
    const size_t ATT_ELEMS = (size_t)B_ * H_ * S_ * S_;

    float* scores_ptr = nullptr;
    cudaGetSymbolAddress((void**)&scores_ptr, g_scores);
    float* wdst = ((size_t)out_size >= OUT_ELEMS + ATT_ELEMS) ? (out + OUT_ELEMS)
                                                              : scores_ptr;

    float *qp, *kp, *vp, *ap;
    cudaGetSymbolAddress((void**)&qp, g_q);
    cudaGetSymbolAddress((void**)&kp, g_kT);
    cudaGetSymbolAddress((void**)&vp, g_v);
    cudaGetSymbolAddress((void**)&ap, g_attn);

    cudaFuncSetAttribute(fused_attn_kernel,
                         cudaFuncAttributeMaxDynamicSharedMemorySize, SMEM_ATTN_BYTES);

    // 1) QKV projection: [4096,1024] @ [1024,3072] -> q / kT / v
    {
        EpiQKV epi{b_qkv};
        tgemm_kernel<EpiQKV><<<dim3(3 * D_ / 128, (B_ * S_) / 128), 128>>>(
            query, W_qkv, D_, D_, 3 * D_, epi);
    }

    // 2) single-pass fused attention (writes unnormalized weights)
    {
        dim3 grid(S_ / 128, B_ * H_);
        fused_attn_kernel<<<grid, 256, SMEM_ATTN_BYTES>>>(qp, kp, vp, wdst, ap);
    }

    // 3) fused tail: out-projection tiles + weight rescale (concurrent blocks)
    {
        int nblocks = TAIL_GEMM_BLOCKS + B_ * H_ * S_;
        fused_tail_kernel<<<nblocks, 128>>>(ap, W_out, b_out, out, wdst);
    }
}

// round 10
// speedup vs baseline: 1.0273x; 1.0273x over previous
#include <cuda_runtime.h>
#include <cstdio>
#include <cstdint>

#define B_ 2
#define S_ 2048
#define D_ 1024
#define H_ 16
#define HD_ 64
#define NKB_ 32   // S_/64 key blocks

// ---------------- scratch (device globals; no allocation allowed) ----------------
__device__ float g_q[(size_t)B_ * H_ * S_ * HD_];     // [B,H,S,Hd]
__device__ float g_kT[(size_t)B_ * H_ * HD_ * S_];    // [B,H,Hd,S]
__device__ float g_v[(size_t)B_ * H_ * S_ * HD_];     // [B,H,S,Hd]
__device__ float g_attn[(size_t)B_ * S_ * D_];        // [B,S,D]
__device__ float g_scores[(size_t)B_ * H_ * S_ * S_]; // fallback weights buffer
__device__ float g_mkb[(size_t)B_ * H_ * NKB_ * S_];  // [bh][kb][s] running max

// ---------------- helpers ----------------
__device__ __forceinline__ uint32_t f2tf32(float x) {
    uint32_t u;
    asm("cvt.rna.tf32.f32 %0, %1;" : "=r"(u) : "f"(x));
    return u;
}

__device__ __forceinline__ void mma_tf32(float& c0, float& c1, float& c2, float& c3,
                                         uint32_t a0, uint32_t a1, uint32_t a2, uint32_t a3,
                                         uint32_t b0, uint32_t b1) {
    asm volatile(
        "mma.sync.aligned.m16n8k8.row.col.f32.tf32.tf32.f32 "
        "{%0,%1,%2,%3}, {%4,%5,%6,%7}, {%8,%9}, {%0,%1,%2,%3};"
        : "+f"(c0), "+f"(c1), "+f"(c2), "+f"(c3)
        : "r"(a0), "r"(a1), "r"(a2), "r"(a3), "r"(b0), "r"(b1));
}

// padded fragment-layout strides (words) to kill staging bank conflicts
#define ASTRIDE 132   // A-frag: 32 lanes x 4 slots = 128 + 4 pad
#define BSTRIDE 66    // B-frag: 32 lanes x 2 slots = 64 + 2 pad

// ---------------- epilogues for projection GEMMs ----------------
struct EpiQKV {
    const float* bias;
    __device__ __forceinline__ void operator()(int m, int n, float v) const {
        v += bias[n];
        int part = n >> 10;
        int rem = n & 1023;
        int h = rem >> 6;
        int d = rem & 63;
        int b = m >> 11;
        int s = m & 2047;
        size_t bh = (size_t)(b * H_ + h);
        if (part == 0)
            g_q[(bh * S_ + s) * HD_ + d] = v;
        else if (part == 1)
            g_kT[(bh * HD_ + d) * S_ + s] = v;
        else
            g_v[(bh * S_ + s) * HD_ + d] = v;
    }
};

struct EpiOut {
    const float* bias;
    float* out;
    __device__ __forceinline__ void operator()(int m, int n, float v) const {
        out[(size_t)m * D_ + n] = v + bias[n];
    }
};

// ---------------- tf32 GEMM: R7 config — 8 warps (64x32), 2-stage pipeline ------
template <int BM, int BN, int WM, int WN, class Epi>
__global__ void __launch_bounds__(256, 2)
tgemm_kernel(const float* __restrict__ A, const float* __restrict__ Bp,
             int K, int lda, int ldb, Epi epi) {
    constexpr int BK = 32;
    constexpr int NWN = BN / WN;
    constexpr int MT = WM / 16;
    constexpr int NT = WN / 8;
    constexpr int A4 = BM * BK / 4 / 256;
    constexpr int B4 = BK * BN / 4 / 256;
    constexpr int AW = (BM / 16) * 4 * ASTRIDE;
    constexpr int BW = (BN / 8) * 4 * BSTRIDE;

    extern __shared__ uint32_t dsm[];

    const int tid = threadIdx.x;
    const int lane = tid & 31;
    const int warp = tid >> 5;
    const int wm = warp / NWN;
    const int wn = warp % NWN;
    const int row0 = blockIdx.y * BM;
    const int col0 = blockIdx.x * BN;

    float acc[MT][NT][4];
#pragma unroll
    for (int i = 0; i < MT; i++)
#pragma unroll
        for (int j = 0; j < NT; j++)
#pragma unroll
            for (int v = 0; v < 4; v++) acc[i][j][v] = 0.f;

    float4 pa[A4], pb[B4];

    auto loadAB = [&](int k0) {
#pragma unroll
        for (int it = 0; it < A4; ++it) {
            int idx = tid + it * 256;
            int r = idx >> 3, c4 = (idx & 7) << 2;
            pa[it] = *reinterpret_cast<const float4*>(
                &A[(size_t)(row0 + r) * lda + k0 + c4]);
        }
#pragma unroll
        for (int it = 0; it < B4; ++it) {
            int idx = tid + it * 256;
            int r = idx / (BN / 4), c4 = (idx % (BN / 4)) << 2;
            pb[it] = *reinterpret_cast<const float4*>(
                &Bp[(size_t)(k0 + r) * ldb + col0 + c4]);
        }
    };

    auto stageAB = [&](uint32_t* sA, uint32_t* sB) {
#pragma unroll
        for (int it = 0; it < A4; ++it) {
            int idx = tid + it * 256;
            int r = idx >> 3, c4 = (idx & 7) << 2;
            int mt = r >> 4, rw = r & 15;
            float vv[4] = {pa[it].x, pa[it].y, pa[it].z, pa[it].w};
#pragma unroll
            for (int j = 0; j < 4; j++) {
                int c = c4 + j;
                int ks = c >> 3, ci = c & 7;
                int ln = ((rw & 7) << 2) | (ci & 3);
                int slot = (rw >> 3) | ((ci >> 2) << 1);
                sA[((mt << 2) + ks) * ASTRIDE + ln * 4 + slot] = f2tf32(vv[j]);
            }
        }
#pragma unroll
        for (int it = 0; it < B4; ++it) {
            int idx = tid + it * 256;
            int r = idx / (BN / 4), c4 = (idx % (BN / 4)) << 2;
            int ks = r >> 3, rw = r & 7;
            float vv[4] = {pb[it].x, pb[it].y, pb[it].z, pb[it].w};
#pragma unroll
            for (int j = 0; j < 4; j++) {
                int n = c4 + j;
                int nt = n >> 3, ci = n & 7;
                int ln = (ci << 2) | (rw & 3);
                int slot = rw >> 2;
                sB[((nt << 2) + ks) * BSTRIDE + ln * 2 + slot] = f2tf32(vv[j]);
            }
        }
    };

    loadAB(0);
    stageAB(dsm, dsm + AW);
    if (BK < K) loadAB(BK);
    __syncthreads();

    for (int k0 = 0; k0 < K; k0 += BK) {
        const int cur = (k0 / BK) & 1;
        uint32_t* cA = cur ? (dsm + AW + BW) : dsm;
        uint32_t* cB = cur ? (dsm + AW + BW + AW) : (dsm + AW);
        uint32_t* nA = cur ? dsm : (dsm + AW + BW);
        uint32_t* nB = cur ? (dsm + AW) : (dsm + AW + BW + AW);

        if (k0 + BK < K) stageAB(nA, nB);
        if (k0 + 2 * BK < K) loadAB(k0 + 2 * BK);

#pragma unroll
        for (int ks = 0; ks < 4; ks++) {
            uint4 af[MT];
            uint2 bf[NT];
#pragma unroll
            for (int i = 0; i < MT; i++)
                af[i] = *reinterpret_cast<const uint4*>(
                    &cA[((wm * MT + i) * 4 + ks) * ASTRIDE + lane * 4]);
#pragma unroll
            for (int j = 0; j < NT; j++)
                bf[j] = *reinterpret_cast<const uint2*>(
                    &cB[((wn * NT + j) * 4 + ks) * BSTRIDE + lane * 2]);
#pragma unroll
            for (int i = 0; i < MT; i++)
#pragma unroll
                for (int j = 0; j < NT; j++)
                    mma_tf32(acc[i][j][0], acc[i][j][1], acc[i][j][2], acc[i][j][3],
                             af[i].x, af[i].y, af[i].z, af[i].w, bf[j].x, bf[j].y);
        }
        __syncthreads();
    }

#pragma unroll
    for (int i = 0; i < MT; i++) {
        int m0 = row0 + wm * WM + i * 16 + (lane >> 2);
#pragma unroll
        for (int j = 0; j < NT; j++) {
            int n0 = col0 + wn * WN + j * 8 + ((lane & 3) << 1);
            epi(m0, n0, acc[i][j][0]);
            epi(m0, n0 + 1, acc[i][j][1]);
            epi(m0 + 8, n0, acc[i][j][2]);
            epi(m0 + 8, n0 + 1, acc[i][j][3]);
        }
    }
}

// ---------------- single-pass flash attention + in-CTA weight rescale -----------
// R7 body; appended final phase: each CTA normalizes its own 128xS weight block
// in place (exp(m_kb - m_fin)/l), using g_mkb[bh][kb][row] + smem m/l finals.
#define SMEM_ATTN_BYTES 104960
__global__ void __launch_bounds__(256, 2)
fused_attn_kernel(const float* __restrict__ qg, const float* __restrict__ kTg,
                  const float* __restrict__ vg, float* __restrict__ wout,
                  float* __restrict__ og) {
    extern __shared__ uint32_t smem[];
    uint32_t* sQ = smem;
    uint32_t* sW = smem + 8448;
    uint32_t* sK = smem + 16896;
    uint32_t* sV = smem + 21120;
    float* sm = (float*)(smem + 25344);
    float* sl = (float*)(smem + 25472);
    float* sredm = (float*)(smem + 25728);
    float* sredl = (float*)(smem + 25984);

    const int tid = threadIdx.x;
    const int lane = tid & 31;
    const int warp = tid >> 5;
    const int wm = warp >> 1;
    const int wn = warp & 1;
    const int g = lane >> 2;
    const int qd = lane & 3;
    const int row0 = blockIdx.x * 128;
    const int bh = blockIdx.y;

    const float* Q = qg + (size_t)bh * S_ * HD_;
    const float* KT = kTg + (size_t)bh * HD_ * S_;
    const float* V = vg + (size_t)bh * S_ * HD_;

    auto stageK = [&](int col0k) {
#pragma unroll
        for (int it = 0; it < 4; it++) {
            int idx = tid + it * 256;
            int r = idx >> 4, c4 = (idx & 15) << 2;
            float4 val = *reinterpret_cast<const float4*>(&KT[(size_t)r * S_ + col0k + c4]);
            int ks = r >> 3, rw = r & 7;
            float vv[4] = {val.x, val.y, val.z, val.w};
#pragma unroll
            for (int j = 0; j < 4; j++) {
                int n = c4 + j, nt = n >> 3, ci = n & 7;
                int ln = (ci << 2) | (rw & 3);
                int slot = rw >> 2;
                sK[((nt << 3) + ks) * BSTRIDE + ln * 2 + slot] = f2tf32(vv[j]);
            }
        }
    };
    auto stageV = [&](int col0k) {
#pragma unroll
        for (int it = 0; it < 4; it++) {
            int idx = tid + it * 256;
            int r = idx >> 4, c4 = (idx & 15) << 2;
            float4 val = *reinterpret_cast<const float4*>(&V[(size_t)(col0k + r) * HD_ + c4]);
            int ks = r >> 3, rw = r & 7;
            float vv[4] = {val.x, val.y, val.z, val.w};
#pragma unroll
            for (int j = 0; j < 4; j++) {
                int n = c4 + j, nt = n >> 3, ci = n & 7;
                int ln = (ci << 2) | (rw & 3);
                int slot = rw >> 2;
                sV[((nt << 3) + ks) * BSTRIDE + ln * 2 + slot] = f2tf32(vv[j]);
            }
        }
    };

#pragma unroll
    for (int it = 0; it < 8; it++) {
        int idx = tid + it * 256;
        int r = idx >> 4, c4 = (idx & 15) << 2;
        float4 val = *reinterpret_cast<const float4*>(&Q[(size_t)(row0 + r) * HD_ + c4]);
        int mt = r >> 4, rw = r & 15;
        float vv[4] = {val.x, val.y, val.z, val.w};
#pragma unroll
        for (int j = 0; j < 4; j++) {
            int c = c4 + j, ks = c >> 3, ci = c & 7;
            int ln = ((rw & 7) << 2) | (ci & 3);
            int slot = (rw >> 3) | ((ci >> 2) << 1);
            sQ[((mt << 3) + ks) * ASTRIDE + ln * 4 + slot] = f2tf32(vv[j] * 0.125f);
        }
    }
    if (tid < 128) { sm[tid] = -1e30f; sl[tid] = 0.f; }
    stageK(0);
    stageV(0);

    float acc_o[2][4][4];
#pragma unroll
    for (int i = 0; i < 2; i++)
#pragma unroll
        for (int j = 0; j < 4; j++)
#pragma unroll
            for (int v = 0; v < 4; v++) acc_o[i][j][v] = 0.f;
    __syncthreads();

    for (int kb = 0; kb < NKB_; kb++) {
        const int col0k = kb * 64;

        float sacc[2][4][4];
#pragma unroll
        for (int i = 0; i < 2; i++)
#pragma unroll
            for (int j = 0; j < 4; j++)
#pragma unroll
                for (int v = 0; v < 4; v++) sacc[i][j][v] = 0.f;
#pragma unroll
        for (int ks = 0; ks < 8; ks++) {
            uint4 af[2];
            uint2 bf[4];
#pragma unroll
            for (int i = 0; i < 2; i++)
                af[i] = *reinterpret_cast<const uint4*>(
                    &sQ[((wm * 2 + i) * 8 + ks) * ASTRIDE + lane * 4]);
#pragma unroll
            for (int j = 0; j < 4; j++)
                bf[j] = *reinterpret_cast<const uint2*>(
                    &sK[((wn * 4 + j) * 8 + ks) * BSTRIDE + lane * 2]);
#pragma unroll
            for (int i = 0; i < 2; i++)
#pragma unroll
                for (int j = 0; j < 4; j++)
                    mma_tf32(sacc[i][j][0], sacc[i][j][1], sacc[i][j][2], sacc[i][j][3],
                             af[i].x, af[i].y, af[i].z, af[i].w, bf[j].x, bf[j].y);
        }

#pragma unroll
        for (int i = 0; i < 2; i++) {
            int r0 = wm * 32 + i * 16 + g;
            float mx0 = -1e30f, mx1 = -1e30f;
#pragma unroll
            for (int j = 0; j < 4; j++) {
                mx0 = fmaxf(mx0, fmaxf(sacc[i][j][0], sacc[i][j][1]));
                mx1 = fmaxf(mx1, fmaxf(sacc[i][j][2], sacc[i][j][3]));
            }
            mx0 = fmaxf(mx0, __shfl_xor_sync(0xffffffffu, mx0, 1));
            mx0 = fmaxf(mx0, __shfl_xor_sync(0xffffffffu, mx0, 2));
            mx1 = fmaxf(mx1, __shfl_xor_sync(0xffffffffu, mx1, 1));
            mx1 = fmaxf(mx1, __shfl_xor_sync(0xffffffffu, mx1, 2));
            if (qd == 0) {
                sredm[wn * 128 + r0] = mx0;
                sredm[wn * 128 + r0 + 8] = mx1;
            }
        }
        __syncthreads();

#pragma unroll
        for (int i = 0; i < 2; i++) {
            int r0 = wm * 32 + i * 16 + g;
            float mo0 = sm[r0], mo1 = sm[r0 + 8];
            float mn0 = fmaxf(mo0, fmaxf(sredm[r0], sredm[128 + r0]));
            float mn1 = fmaxf(mo1, fmaxf(sredm[r0 + 8], sredm[128 + r0 + 8]));
            float a0 = __expf(mo0 - mn0), a1 = __expf(mo1 - mn1);
            float s0 = 0.f, s1 = 0.f;
#pragma unroll
            for (int j = 0; j < 4; j++) {
                int c0 = wn * 32 + j * 8 + qd * 2;
                float p00 = __expf(sacc[i][j][0] - mn0);
                float p01 = __expf(sacc[i][j][1] - mn0);
                float p10 = __expf(sacc[i][j][2] - mn1);
                float p11 = __expf(sacc[i][j][3] - mn1);
                s0 += p00 + p01;
                s1 += p10 + p11;
                size_t base = ((size_t)bh * S_ + row0 + r0) * S_ + col0k + c0;
                float2 q0 = {p00, p01};
                float2 q1 = {p10, p11};
                *reinterpret_cast<float2*>(&wout[base]) = q0;
                *reinterpret_cast<float2*>(&wout[base + (size_t)8 * S_]) = q1;
                {
                    int rr = r0, rw2 = rr & 15, mt = rr >> 4;
                    int c = c0, ks = c >> 3, ci = c & 7;
                    int ln = ((rw2 & 7) << 2) | (ci & 3);
                    int slot = (rw2 >> 3) | ((ci >> 2) << 1);
                    sW[((mt << 3) + ks) * ASTRIDE + ln * 4 + slot] = f2tf32(p00);
                    ci = (c + 1) & 7;
                    ln = ((rw2 & 7) << 2) | (ci & 3);
                    slot = (rw2 >> 3) | ((ci >> 2) << 1);
                    sW[((mt << 3) + ks) * ASTRIDE + ln * 4 + slot] = f2tf32(p01);
                    rr = r0 + 8; rw2 = rr & 15; mt = rr >> 4;
                    ci = c & 7;
                    ln = ((rw2 & 7) << 2) | (ci & 3);
                    slot = (rw2 >> 3) | ((ci >> 2) << 1);
                    sW[((mt << 3) + ks) * ASTRIDE + ln * 4 + slot] = f2tf32(p10);
                    ci = (c + 1) & 7;
                    ln = ((rw2 & 7) << 2) | (ci & 3);
                    slot = (rw2 >> 3) | ((ci >> 2) << 1);
                    sW[((mt << 3) + ks) * ASTRIDE + ln * 4 + slot] = f2tf32(p11);
                }
                acc_o[i][j][0] *= a0; acc_o[i][j][1] *= a0;
                acc_o[i][j][2] *= a1; acc_o[i][j][3] *= a1;
            }
            s0 += __shfl_xor_sync(0xffffffffu, s0, 1);
            s0 += __shfl_xor_sync(0xffffffffu, s0, 2);
            s1 += __shfl_xor_sync(0xffffffffu, s1, 1);
            s1 += __shfl_xor_sync(0xffffffffu, s1, 2);
            if (qd == 0) {
                sredl[wn * 128 + r0] = s0;
                sredl[wn * 128 + r0 + 8] = s1;
            }
        }
        __syncthreads();

        if (tid < 128) {
            float mo = sm[tid];
            float mn = fmaxf(mo, fmaxf(sredm[tid], sredm[128 + tid]));
            sl[tid] = sl[tid] * __expf(mo - mn) + sredl[tid] + sredl[128 + tid];
            sm[tid] = mn;
            // coalesced: [bh][kb][row]
            g_mkb[((size_t)bh * NKB_ + kb) * S_ + row0 + tid] = mn;
        }

        if (kb + 1 < NKB_) stageK(col0k + 64);

#pragma unroll
        for (int ks = 0; ks < 8; ks++) {
            uint4 af[2];
            uint2 bf[4];
#pragma unroll
            for (int i = 0; i < 2; i++)
                af[i] = *reinterpret_cast<const uint4*>(
                    &sW[((wm * 2 + i) * 8 + ks) * ASTRIDE + lane * 4]);
#pragma unroll
            for (int j = 0; j < 4; j++)
                bf[j] = *reinterpret_cast<const uint2*>(
                    &sV[((wn * 4 + j) * 8 + ks) * BSTRIDE + lane * 2]);
#pragma unroll
            for (int i = 0; i < 2; i++)
#pragma unroll
                for (int j = 0; j < 4; j++)
                    mma_tf32(acc_o[i][j][0], acc_o[i][j][1], acc_o[i][j][2], acc_o[i][j][3],
                             af[i].x, af[i].y, af[i].z, af[i].w, bf[j].x, bf[j].y);
        }
        __syncthreads();

        if (kb + 1 < NKB_) stageV(col0k + 64);
    }

    // finals: invert l (smem only)
    if (tid < 128) sl[tid] = 1.0f / sl[tid];
    __syncthreads();

    // O epilogue
    const int b = bh >> 4;
    const int h = bh & 15;
#pragma unroll
    for (int i = 0; i < 2; i++) {
        int r0 = wm * 32 + i * 16 + g;
        float il0 = sl[r0], il1 = sl[r0 + 8];
        int gr = row0 + r0;
#pragma unroll
        for (int j = 0; j < 4; j++) {
            int c0 = wn * 32 + j * 8 + qd * 2;
            float2 p0 = {acc_o[i][j][0] * il0, acc_o[i][j][1] * il0};
            float2 p1 = {acc_o[i][j][2] * il1, acc_o[i][j][3] * il1};
            size_t a0 = (((size_t)b * S_ + gr) * H_ + h) * HD_ + c0;
            size_t a1 = (((size_t)b * S_ + gr + 8) * H_ + h) * HD_ + c0;
            *reinterpret_cast<float2*>(&og[a0]) = p0;
            *reinterpret_cast<float2*>(&og[a1]) = p1;
        }
    }

    // ---- in-CTA weight rescale: w *= exp(m_kb - m_fin) / l (in place) ----
    {
        const int rr = tid >> 1;              // 0..127
        const int chalf = (tid & 1) << 5;     // 0 or 32
        const float mfin = sm[rr];
        const float il = sl[rr];
        float* wrow = wout + ((size_t)bh * S_ + row0 + rr) * S_ + chalf;
        const float* mkrow = &g_mkb[(size_t)bh * NKB_ * S_ + row0 + rr];
        for (int kb = 0; kb < NKB_; kb++) {
            float fac = __expf(mkrow[(size_t)kb * S_] - mfin) * il;
            float* p = wrow + kb * 64;
#pragma unroll
            for (int c4 = 0; c4 < 8; c4++) {
                float4 a = *reinterpret_cast<const float4*>(p + c4 * 4);
                a.x *= fac; a.y *= fac; a.z *= fac; a.w *= fac;
                *reinterpret_cast<float4*>(p + c4 * 4) = a;
            }
        }
    }
}

// ---------------- launch ----------------
extern "C" void kernel_launch(void* const* d_in, const int* in_sizes, int n_in,
                              void* d_out, int out_size) {
    const float* query = (const float*)d_in[0];
    const float* W_qkv = (const float*)d_in[1];
    const float* b_qkv = (const float*)d_in[2];
    const float* W_out = (const float*)d_in[3];
    const float* b_out = (const float*)d_in[4];
    float* out = (float*)d_out;

    const size_t OUT_ELEMS = (size_t)B_ * S_ * D_;
    const size_t ATT_ELEMS = (size_t)B_ * H_ * S_ * S_;

    float* scores_ptr = nullptr;
    cudaGetSymbolAddress((void**)&scores_ptr, g_scores);
    float* wdst = ((size_t)out_size >= OUT_ELEMS + ATT_ELEMS) ? (out + OUT_ELEMS)
                                                              : scores_ptr;

    float *qp, *kp, *vp, *ap;
    cudaGetSymbolAddress((void**)&qp, g_q);
    cudaGetSymbolAddress((void**)&kp, g_kT);
    cudaGetSymbolAddress((void**)&vp, g_v);
    cudaGetSymbolAddress((void**)&ap, g_attn);

    // 2 buffers x (sA 4224 + sB 4224 words) = 67584 bytes for 128x128 tiles
    const int TG_SMEM = 2 * ((128 / 16) * 4 * 132 + (128 / 8) * 4 * 66) * 4;

    cudaFuncSetAttribute(fused_attn_kernel,
                         cudaFuncAttributeMaxDynamicSharedMemorySize, SMEM_ATTN_BYTES);
    cudaFuncSetAttribute(tgemm_kernel<128, 128, 64, 32, EpiQKV>,
                         cudaFuncAttributeMaxDynamicSharedMemorySize, TG_SMEM);
    cudaFuncSetAttribute(tgemm_kernel<128, 128, 64, 32, EpiOut>,
                         cudaFuncAttributeMaxDynamicSharedMemorySize, TG_SMEM);

    // 1) QKV projection
    {
        EpiQKV epi{b_qkv};
        tgemm_kernel<128, 128, 64, 32, EpiQKV>
            <<<dim3(3 * D_ / 128, (B_ * S_) / 128), 256, TG_SMEM>>>(
                query, W_qkv, D_, D_, 3 * D_, epi);
    }

    // 2) fused attention: scores + softmax + weights (normalized in-CTA) + AV
    {
        dim3 grid(S_ / 128, B_ * H_);
        fused_attn_kernel<<<grid, 256, SMEM_ATTN_BYTES>>>(qp, kp, vp, wdst, ap);
    }

    // 3) out projection
    {
        EpiOut epi{b_out, out};
        tgemm_kernel<128, 128, 64, 32, EpiOut>
            <<<dim3(D_ / 128, (B_ * S_) / 128), 256, TG_SMEM>>>(
                ap, W_out, D_, D_, D_, epi);
    }
}